// round 17
// baseline (speedup 1.0000x reference)
#include <cuda_runtime.h>
#include <cuda_fp16.h>
#include <cstdint>

// SpatialConv implicit GEMM, fp16 mma.sync.m16n8k16 (f32 accum).
// A fragments loaded DIRECTLY from gmem (fragment-packed LDG.128, rolling
// prefetch). X staged via 3-stage cp.async, 32-channel chunks (8 barriers).
// CTA: 64 Co x 128 px (2 rows), 256 thr, 8 warps, warp tile 32x32.
// 2048 CTAs / 296 slots = 6.92 waves -> ~1% tail (vs 15.6% at 1024).
// taps: 0:(0,0) 1:(-1,0) 2:(0,-1) 3:(0,1) 4:(1,0)

#define CI 256
#define CO 256
#define HH 64
#define WW 64
#define NB 16
#define NTH 256
#define NCHK 8               // 32-channel chunks
#define X_SUB 2304           // u32 per 16-ch sub-block: [row4][col72][s8]
#define X_ST (2 * X_SUB)     // 4608 u32 per stage
#define NSTG 3
#define DYN ((NSTG * X_ST) * 4)   // 55296 B

// g_wti: [cob2][chk16][tap5][blk8][gid8][tig4][j4] u32 (fragment-packed half2)
__device__ __align__(16) uint32_t g_wti[163840];
// g_x2: [n16][chk16][h64][w64][s8] u32 ; s -> cp_local = (s>>1)+(s&1)*4
__device__ __align__(16) uint32_t g_x2[(size_t)NB * 16 * HH * WW * 8];

#define XWARPS (NB * 16 * HH)
#define XBLKS (XWARPS / 8)               // 2048
#define WBLKS 640

__global__ void prep(const float* __restrict__ x, const float* __restrict__ wt) {
    if (blockIdx.x < XBLKS) {
        int gw = blockIdx.x * 8 + (threadIdx.x >> 5);
        int lane = threadIdx.x & 31;
        int h = gw & 63, chk = (gw >> 6) & 15, n = gw >> 10;
        const float* xb = x + (((size_t)n * CI + chk * 16) * HH + h) * WW;
#pragma unroll
        for (int half = 0; half < 2; half++) {
            int w = half * 32 + lane;
            float v[16];
#pragma unroll
            for (int c = 0; c < 16; c++)
                v[c] = xb[(size_t)c * HH * WW + w];
            uint32_t p[8];
#pragma unroll
            for (int s = 0; s < 8; s++) {
                int cp = (s >> 1) + (s & 1) * 4;
                __half2 hv = __floats2half2_rn(v[2 * cp], v[2 * cp + 1]);
                p[s] = *(uint32_t*)&hv;
            }
            uint32_t* dst = g_x2 + ((((size_t)(n * 16 + chk) * HH + h) * WW + w) << 3);
            *(uint4*)dst       = make_uint4(p[0], p[1], p[2], p[3]);
            *(uint4*)(dst + 4) = make_uint4(p[4], p[5], p[6], p[7]);
        }
    } else {
        int idx = (int)(blockIdx.x - XBLKS) * 256 + threadIdx.x;
        if (idx >= 163840) return;
        int j   = idx & 3, tig = (idx >> 2) & 3, gid = (idx >> 4) & 7;
        int blk = (idx >> 7) & 7, tap = (idx >> 10) % 5;
        int rest = idx / (5 << 10);
        int chk = rest & 15, cob = rest >> 4;
        int o  = cob * 128 + blk * 16 + gid + (j & 1) * 8;
        int cp = chk * 8 + tig + (j >> 1) * 4;
        float a = wt[(size_t)o * 1280 + (2 * cp) * 5 + tap];
        float bb = wt[(size_t)o * 1280 + (2 * cp + 1) * 5 + tap];
        __half2 hv = __floats2half2_rn(a, bb);
        g_wti[idx] = *(uint32_t*)&hv;
    }
}

__device__ __forceinline__ void cpa16(uint32_t dst, const void* src, int srcsz) {
    asm volatile("cp.async.cg.shared.global [%0], [%1], 16, %2;"
                 :: "r"(dst), "l"(src), "r"(srcsz));
}

__global__ __launch_bounds__(NTH, 2)
void conv_mma_kernel(float* __restrict__ out)
{
    extern __shared__ uint32_t sm[];
    const int tid  = threadIdx.x;
    const int lane = tid & 31, wid = tid >> 5;
    const int wm   = wid >> 2;        // 0..1 : 32-co tile within 64
    const int wq   = wid & 3;
    const int wn   = wq >> 1;         // 0..1 : output row
    const int chf  = wq & 1;          // 0..1 : 32-px column half
    const int gid  = lane >> 2, tig = lane & 3;
    const int cbi  = blockIdx.x;      // 0..3 : 64-co tile
    const int h0   = blockIdx.y * 2;
    const int n    = blockIdx.z;

    uint32_t* Xbuf = sm;
    const uint32_t xB = (uint32_t)__cvta_generic_to_shared(sm);

    // A-fragment base: g_wti[cob2][s16][tap][blk8][gid][tig][j]
    const uint32_t* aptr = g_wti + (size_t)(cbi >> 1) * 81920 + gid * 16 + tig * 4;
    const int blkbase = (cbi & 1) * 4 + wm * 2;   // + mi

    // zero X border cols (0..3, 68..71): 2 subs x 4 rows per stage
    for (int e = tid; e < NSTG * 2 * 4 * 8 * 8; e += NTH) {
        int st = e / 512, r2 = e % 512;
        int sub = r2 >> 8, r = (r2 >> 6) & 3, cq = (r2 >> 3) & 7, s = r2 & 7;
        int col = (cq < 4) ? cq : (64 + cq);
        Xbuf[st * X_ST + sub * X_SUB + r * 576 + col * 8 + s] = 0;
    }

    float acc[2][4][4];
#pragma unroll
    for (int mi = 0; mi < 2; mi++)
#pragma unroll
        for (int ni = 0; ni < 4; ni++)
#pragma unroll
            for (int r = 0; r < 4; r++) acc[mi][ni][r] = 0.f;

    auto stageX = [&](int chk, int st) {
#pragma unroll
        for (int sub = 0; sub < 2; sub++) {
#pragma unroll
            for (int i = 0; i < 2; i++) {
                int e = tid + i * NTH;
                int r = e >> 7, k = e & 127;
                int gh = h0 - 1 + r;
                int ok = ((unsigned)gh < HH) ? 16 : 0;
                int ghc = ok ? gh : 0;
                cpa16(xB + (uint32_t)((st * X_ST + sub * X_SUB + r * 576 + 32 + k * 4) * 4),
                      g_x2 + ((((size_t)(n * 16 + chk * 2 + sub) * HH + ghc) * WW) * 8 + k * 4), ok);
            }
        }
    };

    stageX(0, 0);
    asm volatile("cp.async.commit_group;");
    stageX(1, 1);
    asm volatile("cp.async.commit_group;");

    const int ROW[5] = {1, 0, 1, 1, 2};
    const int DX5[5] = {0, 0, -1, 1, 0};

    // prologue: A frags for (sub16=0, tap=0)
    uint32_t acur[2][4], anxt[2][4];
#pragma unroll
    for (int mi = 0; mi < 2; mi++) {
        uint4 v = *(const uint4*)&aptr[(blkbase + mi) * 128];
        acur[mi][0] = v.x; acur[mi][1] = v.y; acur[mi][2] = v.z; acur[mi][3] = v.w;
    }

    for (int chk = 0; chk < NCHK; chk++) {
        const int st = chk % NSTG;
        asm volatile("cp.async.wait_group 1;");
        __syncthreads();

        if (chk + 2 < NCHK) stageX(chk + 2, (chk + 2) % NSTG);
        asm volatile("cp.async.commit_group;");

        const uint32_t* Xs = Xbuf + st * X_ST;

#pragma unroll
        for (int kb = 0; kb < 10; kb++) {
            const int sub = (kb < 5) ? 0 : 1;
            const int tap = (kb < 5) ? kb : kb - 5;

            // prefetch A frags for next step
            {
                int kn = kb + 1;
                int cn = chk, sn = (kn < 5) ? 0 : 1, tn = (kn < 5) ? kn : kn - 5;
                if (kn == 10) { cn = (chk + 1 < NCHK) ? chk + 1 : chk; sn = 0; tn = 0; }
                int s16 = cn * 2 + sn;
#pragma unroll
                for (int mi = 0; mi < 2; mi++) {
                    uint4 v = *(const uint4*)&aptr[s16 * 5120 + tn * 1024 + (blkbase + mi) * 128];
                    anxt[mi][0] = v.x; anxt[mi][1] = v.y; anxt[mi][2] = v.z; anxt[mi][3] = v.w;
                }
            }

            const int rr = ROW[tap] + wn;
            const int dx = DX5[tap];
            const uint32_t* X = Xs + sub * X_SUB;
            uint32_t b[4][2];
#pragma unroll
            for (int ni = 0; ni < 4; ni++) {
                int col = chf * 32 + ni * 8 + gid + 4 + dx;
                uint2 v = *(const uint2*)&X[rr * 576 + col * 8 + tig * 2];
                b[ni][0] = v.x; b[ni][1] = v.y;
            }
#pragma unroll
            for (int mi = 0; mi < 2; mi++)
#pragma unroll
                for (int ni = 0; ni < 4; ni++) {
                    asm volatile(
                        "mma.sync.aligned.m16n8k16.row.col.f32.f16.f16.f32 "
                        "{%0,%1,%2,%3}, {%4,%5,%6,%7}, {%8,%9}, {%0,%1,%2,%3};"
                        : "+f"(acc[mi][ni][0]), "+f"(acc[mi][ni][1]),
                          "+f"(acc[mi][ni][2]), "+f"(acc[mi][ni][3])
                        : "r"(acur[mi][0]), "r"(acur[mi][1]), "r"(acur[mi][2]), "r"(acur[mi][3]),
                          "r"(b[ni][0]), "r"(b[ni][1]));
                }
#pragma unroll
            for (int mi = 0; mi < 2; mi++)
#pragma unroll
                for (int j = 0; j < 4; j++) acur[mi][j] = anxt[mi][j];
        }
    }

    // epilogue: warp owns row h0+wn, col half chf
    const int h = h0 + wn;
#pragma unroll
    for (int mi = 0; mi < 2; mi++) {
        int co0 = cbi * 64 + wm * 32 + mi * 16 + gid;
#pragma unroll
        for (int ni = 0; ni < 4; ni++) {
            int c0 = chf * 32 + ni * 8 + tig * 2;
            *(float2*)&out[(((size_t)n * CO + co0) * HH + h) * WW + c0] =
                make_float2(acc[mi][ni][0], acc[mi][ni][1]);
            *(float2*)&out[(((size_t)n * CO + co0 + 8) * HH + h) * WW + c0] =
                make_float2(acc[mi][ni][2], acc[mi][ni][3]);
        }
    }
}

extern "C" void kernel_launch(void* const* d_in, const int* in_sizes, int n_in,
                              void* d_out, int out_size)
{
    const float* x  = (const float*)d_in[0];
    const float* wt = (const float*)d_in[1];
    float* out = (float*)d_out;

    prep<<<XBLKS + WBLKS, 256>>>(x, wt);

    cudaFuncSetAttribute(conv_mma_kernel,
                         cudaFuncAttributeMaxDynamicSharedMemorySize, DYN);
    dim3 grid(CO / 64, HH / 2, NB);   // (4, 32, 16) = 2048 CTAs
    conv_mma_kernel<<<grid, NTH, DYN>>>(out);
}